// round 6
// baseline (speedup 1.0000x reference)
#include <cuda_runtime.h>
#include <cuda_bf16.h>
#include <math.h>

// Problem constants
#define NN   50000
#define EE   800000
#define NMOL 2000
#define INRR 64
#define OUTD 128
#define EDD  16
#define CLSD 256
#define HSW  640   // OUT*(L_CONV+1)

// Static scratch (no allocations allowed)
__device__ float g_agg[(size_t)NN * 128];
__device__ float g_h0[(size_t)NN * 128];
__device__ float g_HS[(size_t)NN * HSW];
__device__ float g_pool[(size_t)NMOL * 128];
__device__ float g_z1[(size_t)NN * CLSD];
__device__ float g_z2[(size_t)NN * CLSD];
// CSR (by dst) — g_cnt must be zero on entry to each call (zero at load,
// re-zeroed by csr_scan each call).
__device__ int g_cnt[NN];
__device__ int g_off[NN + 1];
__device__ int g_cur[NN];
__device__ int g_srcs[EE];                       // CSR-ordered src node
__device__ float g_attrs[(size_t)EE * 16];       // CSR-ordered edge_attr

// Pre-converted packed bf16 weights (hi/lo split).
// word(kp, m) = pack(bf16(B[2kp][m]), bf16(B[2kp+1][m])), low half = even k.
#define WC1_OFF   0                 // conv1W:  Kp=32,  M=128 -> 4096
#define WCV_OFF   4096              // convW i: Kp=64,  M=128 -> 8192 each (x4)
#define WK1_OFF   36864             // cls1W:   Kp=320, M=256 -> 81920
#define WK2_OFF   118784            // kW[0]:   Kp=128, M=256 -> 32768
#define WK3_OFF   151552            // kW[1]:   Kp=128, M=256 -> 32768
#define WTOT      184320
__device__ unsigned g_Bh[WTOT];
__device__ unsigned g_Bl[WTOT];

__device__ __forceinline__ float dleaky(float v) {
    float t = v > 0.f ? v : 0.01f * v;
    return t > 0.f ? t : 0.01f * t;
}
__device__ __forceinline__ float leaky1(float v) {
    return v > 0.f ? v : 0.01f * v;
}

// f32x2 helpers
__device__ __forceinline__ unsigned long long packf2(float lo, float hi) {
    unsigned long long r;
    asm("mov.b64 %0, {%1, %2};" : "=l"(r) : "r"(__float_as_uint(lo)), "r"(__float_as_uint(hi)));
    return r;
}
__device__ __forceinline__ unsigned long long dupf2(float v) {
    unsigned long long r;
    unsigned b = __float_as_uint(v);
    asm("mov.b64 %0, {%1, %1};" : "=l"(r) : "r"(b));
    return r;
}
__device__ __forceinline__ void fma2(unsigned long long& d,
                                     unsigned long long a, unsigned long long b) {
    asm("fma.rn.f32x2 %0, %1, %2, %0;" : "+l"(d) : "l"(a), "l"(b));
}
__device__ __forceinline__ void unpackf2(unsigned long long v, float& lo, float& hi) {
    unsigned ulo, uhi;
    asm("mov.b64 {%0, %1}, %2;" : "=r"(ulo), "=r"(uhi) : "l"(v));
    lo = __uint_as_float(ulo);
    hi = __uint_as_float(uhi);
}

__device__ __forceinline__ unsigned pack_bf16(float lo, float hi) {
    __nv_bfloat162 h = __floats2bfloat162_rn(lo, hi);
    return *(unsigned*)&h;
}

// ---------------------------------------------------------------------------
// Fused kernel: blocks [0, CNT_BLK) count edge dst; blocks [CNT_BLK, ...)
// convert weight matrices to packed bf16 hi/lo.
// ---------------------------------------------------------------------------
#define CNT_BLK 3125                 // ceil(EE/256)
#define WCVT_BLK 720                 // ceil(WTOT/256)

__global__ void wcvt_count_kernel(const int* __restrict__ dstv,
                                  const float* __restrict__ c1W,
                                  const float* __restrict__ cW,
                                  const float* __restrict__ k1W,
                                  const float* __restrict__ kW) {
    if (blockIdx.x < CNT_BLK) {
        int e = blockIdx.x * blockDim.x + threadIdx.x;
        if (e < EE) atomicAdd(&g_cnt[dstv[e]], 1);
        return;
    }
    int widx = (blockIdx.x - CNT_BLK) * blockDim.x + threadIdx.x;
    if (widx >= WTOT) return;
    const float* src;
    int M, kp, m;
    if (widx < WCV_OFF) {                         // conv1W
        src = c1W; M = 128;
        kp = widx >> 7; m = widx & 127;
    } else if (widx < WK1_OFF) {                  // convW[i]
        int r = widx - WCV_OFF;
        int i = r >> 13; r &= 8191;
        src = cW + (size_t)i * OUTD * OUTD; M = 128;
        kp = r >> 7; m = r & 127;
    } else if (widx < WK2_OFF) {                  // cls1W
        int r = widx - WK1_OFF;
        src = k1W; M = 256;
        kp = r >> 8; m = r & 255;
    } else if (widx < WK3_OFF) {                  // kW[0]
        int r = widx - WK2_OFF;
        src = kW; M = 256;
        kp = r >> 8; m = r & 255;
    } else {                                      // kW[1]
        int r = widx - WK3_OFF;
        src = kW + CLSD * CLSD; M = 256;
        kp = r >> 8; m = r & 255;
    }
    float v0 = src[(size_t)(2 * kp) * M + m];
    float v1 = src[(size_t)(2 * kp + 1) * M + m];
    float h0 = __bfloat162float(__float2bfloat16(v0));
    float h1 = __bfloat162float(__float2bfloat16(v1));
    g_Bh[widx] = pack_bf16(h0, h1);
    g_Bl[widx] = pack_bf16(v0 - h0, v1 - h1);
}

// ---------------------------------------------------------------------------
// Scan: g_cnt -> g_off/g_cur, then zero g_cnt (invariant for next call)
// ---------------------------------------------------------------------------
__global__ void csr_scan_kernel() {
    __shared__ int part[1024];
    const int CH = (NN + 1023) / 1024;
    int t = threadIdx.x;
    int start = t * CH;
    int sum = 0;
    for (int i = 0; i < CH; i++) {
        int idx = start + i;
        if (idx < NN) sum += g_cnt[idx];
    }
    part[t] = sum;
    __syncthreads();
    for (int o = 1; o < 1024; o <<= 1) {
        int v = (t >= o) ? part[t - o] : 0;
        __syncthreads();
        part[t] += v;
        __syncthreads();
    }
    int run = part[t] - sum;
    for (int i = 0; i < CH; i++) {
        int idx = start + i;
        if (idx < NN) {
            g_off[idx] = run;
            g_cur[idx] = run;
            run += g_cnt[idx];
            g_cnt[idx] = 0;          // restore invariant
        }
    }
    if (t == 0) g_off[NN] = EE;
}

// ---------------------------------------------------------------------------
// Fill + permute fused: 4 threads per edge. Leader does atomicAdd on g_cur,
// pos broadcast via intra-quad shfl; all 4 write 16B of attr + leader src.
// ---------------------------------------------------------------------------
__global__ void fill_permute_kernel(const int* __restrict__ srcv,
                                    const int* __restrict__ dstv,
                                    const float* __restrict__ attr) {
    int idx = blockIdx.x * blockDim.x + threadIdx.x;   // EE*4
    if (idx >= EE * 4) return;
    int e = idx >> 2, c4 = idx & 3;
    int lane = threadIdx.x & 31;
    int pos = 0;
    if (c4 == 0) pos = atomicAdd(&g_cur[dstv[e]], 1);
    pos = __shfl_sync(0xffffffffu, pos, lane & ~3);
    float4 v = __ldg((const float4*)&attr[(size_t)e * 16 + c4 * 4]);
    *(float4*)&g_attrs[(size_t)pos * 16 + c4 * 4] = v;
    if (c4 == 0) g_srcs[pos] = __ldg(&srcv[e]);
}

// ---------------------------------------------------------------------------
// Gather-based edge aggregation: warp per node, depth-3 pair pipeline.
//   agg[n] = x[n] + sum_{e: dst=n} relu(x[src[e]] + attr[e]@eW + eb)
// ---------------------------------------------------------------------------
template <int D>
__global__ __launch_bounds__(128)
void gather_kernel(const float* __restrict__ x, int ldx,
                   const float* __restrict__ eW,
                   const float* __restrict__ eb,
                   float* __restrict__ agg) {
    constexpr int C = D / 32;                 // floats per lane (2 or 4)
    constexpr int P = C / 2;                  // f32x2 pairs per lane
    const int lane = threadIdx.x & 31;
    int n = (blockIdx.x * blockDim.x + threadIdx.x) >> 5;
    if (n >= NN) return;

    unsigned long long wp[16 * P];
#pragma unroll
    for (int k = 0; k < 16; k++)
#pragma unroll
        for (int p = 0; p < P; p++) {
            float2 w2 = *(const float2*)&eW[k * D + lane * C + 2 * p];
            wp[k * P + p] = packf2(w2.x, w2.y);
        }
    unsigned long long ebp[P];
#pragma unroll
    for (int p = 0; p < P; p++) {
        float2 b2 = *(const float2*)&eb[lane * C + 2 * p];
        ebp[p] = packf2(b2.x, b2.y);
    }

    float acc[C];
    if constexpr (C == 4) {
        float4 xv = *(const float4*)&x[(size_t)n * ldx + lane * 4];
        acc[0] = xv.x; acc[1] = xv.y; acc[2] = xv.z; acc[3] = xv.w;
    } else {
        float2 xv = *(const float2*)&x[(size_t)n * ldx + lane * 2];
        acc[0] = xv.x; acc[1] = xv.y;
    }

    const int i1 = g_off[n + 1];
    int i0 = g_off[n];

    float x0a[C], x0b[C], x1a[C], x1b[C], x2a[C], x2b[C];

    auto ld_x = [&](int pos, float (&xr)[C]) {
        if (pos < i1) {
            int s = __ldg(&g_srcs[pos]);
            if constexpr (C == 4) {
                float4 v = *(const float4*)&x[(size_t)s * ldx + lane * 4];
                xr[0] = v.x; xr[1] = v.y; xr[2] = v.z; xr[3] = v.w;
            } else {
                float2 v = *(const float2*)&x[(size_t)s * ldx + lane * 2];
                xr[0] = v.x; xr[1] = v.y;
            }
        }
    };

    auto process = [&](int pos, const float (&xr)[C]) {
        const float4* ap = (const float4*)&g_attrs[(size_t)pos * 16];
        float4 A0 = __ldg(ap + 0);
        float4 A1 = __ldg(ap + 1);
        float4 A2 = __ldg(ap + 2);
        float4 A3 = __ldg(ap + 3);
        unsigned long long e[P];
#pragma unroll
        for (int p = 0; p < P; p++) e[p] = ebp[p];
        float av[16] = {A0.x, A0.y, A0.z, A0.w, A1.x, A1.y, A1.z, A1.w,
                        A2.x, A2.y, A2.z, A2.w, A3.x, A3.y, A3.z, A3.w};
#pragma unroll
        for (int k = 0; k < 16; k++) {
            unsigned long long av2 = dupf2(av[k]);
#pragma unroll
            for (int p = 0; p < P; p++) fma2(e[p], av2, wp[k * P + p]);
        }
#pragma unroll
        for (int p = 0; p < P; p++) {
            float lo, hi;
            unpackf2(e[p], lo, hi);
            float m0 = xr[2 * p] + lo;
            float m1 = xr[2 * p + 1] + hi;
            acc[2 * p] += m0 > 0.f ? m0 : 0.f;
            acc[2 * p + 1] += m1 > 0.f ? m1 : 0.f;
        }
    };

    if (i0 < i1) {
        ld_x(i0, x0a);     ld_x(i0 + 1, x0b);
        ld_x(i0 + 2, x1a); ld_x(i0 + 3, x1b);
        for (int base = i0; base < i1; base += 2) {
            ld_x(base + 4, x2a);
            ld_x(base + 5, x2b);
            process(base, x0a);
            if (base + 1 < i1) process(base + 1, x0b);
#pragma unroll
            for (int c = 0; c < C; c++) {
                x0a[c] = x1a[c]; x0b[c] = x1b[c];
                x1a[c] = x2a[c]; x1b[c] = x2b[c];
            }
        }
    }

    if constexpr (C == 4) {
        *(float4*)&g_agg[(size_t)n * D + lane * 4] =
            make_float4(acc[0], acc[1], acc[2], acc[3]);
    } else {
        *(float2*)&g_agg[(size_t)n * D + lane * 2] = make_float2(acc[0], acc[1]);
    }
}

// ---------------------------------------------------------------------------
// Split-bf16 tensor-core GEMM with pre-converted packed B.
//   C = act(scale(A[N,K] @ B[K,M] + bias));  C ≈ Ah*Bh + Ah*Bl + Al*Bh
// B comes from g_Bh/g_Bl at word layout [K/2][M].
// ---------------------------------------------------------------------------
__device__ __forceinline__ void mma_bf16(float* acc, const unsigned* a, const unsigned* b) {
    asm volatile(
        "mma.sync.aligned.m16n8k16.row.col.f32.bf16.bf16.f32 "
        "{%0,%1,%2,%3}, {%4,%5,%6,%7}, {%8,%9}, {%0,%1,%2,%3};"
        : "+f"(acc[0]), "+f"(acc[1]), "+f"(acc[2]), "+f"(acc[3])
        : "r"(a[0]), "r"(a[1]), "r"(a[2]), "r"(a[3]), "r"(b[0]), "r"(b[1]));
}

template <int ACT>
__global__ __launch_bounds__(256)
void bf16_gemm(const float* __restrict__ A, int lda,
               const unsigned* __restrict__ PBh,
               const unsigned* __restrict__ PBl,
               const float* __restrict__ bias,
               const float* __restrict__ gamma,
               const float* __restrict__ beta,
               float* __restrict__ Cmat, int ldc,
               int Nrows, int K, int M, float bn_inv) {
    __shared__ unsigned sAh[128][9];
    __shared__ unsigned sAl[128][9];
    __shared__ unsigned sBh[128][9];
    __shared__ unsigned sBl[128][9];

    const int tid = threadIdx.x;
    const int lane = tid & 31;
    const int wid = tid >> 5;
    const int wm = (wid & 1) * 64;
    const int wn = (wid >> 1) * 32;
    const int row0 = blockIdx.y * 128;
    const int col0 = blockIdx.x * 128;

    float acc[16][4];
#pragma unroll
    for (int i = 0; i < 16; i++)
#pragma unroll
        for (int j = 0; j < 4; j++) acc[i][j] = 0.f;

    float4 ga[2];
    uint2 gh[2], gl[2];

    auto load_tile = [&](int k0) {
#pragma unroll
        for (int j = 0; j < 2; j++) {
            int idx = j * 256 + tid;
            int m = idx >> 2, kk = (idx & 3) << 2;
            int r = row0 + m;
            ga[j] = make_float4(0.f, 0.f, 0.f, 0.f);
            if (r < Nrows) ga[j] = *(const float4*)&A[(size_t)r * lda + k0 + kk];
            int n = (idx & 63) << 1, bkp = idx >> 6;
            size_t off = (size_t)(k0 / 2 + bkp) * M + col0 + n;
            gh[j] = *(const uint2*)&PBh[off];
            gl[j] = *(const uint2*)&PBl[off];
        }
    };

    load_tile(0);

    for (int k0 = 0; k0 < K; k0 += 16) {
        __syncthreads();
#pragma unroll
        for (int j = 0; j < 2; j++) {
            int idx = j * 256 + tid;
            int m = idx >> 2, kp = (idx & 3) << 1;
            float4 v = ga[j];
            float hx = __bfloat162float(__float2bfloat16(v.x));
            float hy = __bfloat162float(__float2bfloat16(v.y));
            float hz = __bfloat162float(__float2bfloat16(v.z));
            float hw = __bfloat162float(__float2bfloat16(v.w));
            sAh[m][kp]     = pack_bf16(hx, hy);
            sAh[m][kp + 1] = pack_bf16(hz, hw);
            sAl[m][kp]     = pack_bf16(v.x - hx, v.y - hy);
            sAl[m][kp + 1] = pack_bf16(v.z - hz, v.w - hw);

            int n = (idx & 63) << 1, bkp = idx >> 6;
            sBh[n][bkp]     = gh[j].x;
            sBh[n + 1][bkp] = gh[j].y;
            sBl[n][bkp]     = gl[j].x;
            sBl[n + 1][bkp] = gl[j].y;
        }
        __syncthreads();

        if (k0 + 16 < K) load_tile(k0 + 16);

        unsigned af[4][4], bh[4][2], bl[4][2];
        const int ar = lane >> 2, ak = lane & 3;
#pragma unroll
        for (int i = 0; i < 4; i++) {
            int m = wm + i * 16 + ar;
            af[i][0] = sAh[m][ak];
            af[i][1] = sAh[m + 8][ak];
            af[i][2] = sAh[m][ak + 4];
            af[i][3] = sAh[m + 8][ak + 4];
        }
#pragma unroll
        for (int j = 0; j < 4; j++) {
            int nn = wn + j * 8 + (lane >> 2);
            bh[j][0] = sBh[nn][lane & 3];
            bh[j][1] = sBh[nn][(lane & 3) + 4];
            bl[j][0] = sBl[nn][lane & 3];
            bl[j][1] = sBl[nn][(lane & 3) + 4];
        }
#pragma unroll
        for (int i = 0; i < 4; i++)
#pragma unroll
            for (int j = 0; j < 4; j++) mma_bf16(acc[i * 4 + j], af[i], bh[j]);
#pragma unroll
        for (int i = 0; i < 4; i++)
#pragma unroll
            for (int j = 0; j < 4; j++) mma_bf16(acc[i * 4 + j], af[i], bl[j]);
#pragma unroll
        for (int i = 0; i < 4; i++) {
            int m = wm + i * 16 + ar;
            af[i][0] = sAl[m][ak];
            af[i][1] = sAl[m + 8][ak];
            af[i][2] = sAl[m][ak + 4];
            af[i][3] = sAl[m + 8][ak + 4];
        }
#pragma unroll
        for (int i = 0; i < 4; i++)
#pragma unroll
            for (int j = 0; j < 4; j++) mma_bf16(acc[i * 4 + j], af[i], bh[j]);
    }

    // epilogue
#pragma unroll
    for (int i = 0; i < 4; i++) {
#pragma unroll
        for (int j = 0; j < 4; j++) {
            int r = row0 + wm + i * 16 + (lane >> 2);
            int c = col0 + wn + j * 8 + (lane & 3) * 2;
            float* ap = acc[i * 4 + j];
#pragma unroll
            for (int h = 0; h < 2; h++) {
                int rr = r + h * 8;
                if (rr >= Nrows) continue;
                float v0 = ap[h * 2 + 0] + bias[c];
                float v1 = ap[h * 2 + 1] + bias[c + 1];
                if (gamma != nullptr) {
                    v0 = gamma[c] * (v0 * bn_inv) + beta[c];
                    v1 = gamma[c + 1] * (v1 * bn_inv) + beta[c + 1];
                }
                if (ACT == 1) { v0 = leaky1(v0); v1 = leaky1(v1); }
                else if (ACT == 2) { v0 = dleaky(v0); v1 = dleaky(v1); }
                *(float2*)&Cmat[(size_t)rr * ldc + c] = make_float2(v0, v1);
            }
        }
    }
}

// ---------------------------------------------------------------------------
// Pooling
// ---------------------------------------------------------------------------
__global__ void zero_pool_kernel() {
    int idx = blockIdx.x * blockDim.x + threadIdx.x;
    if (idx < NMOL * 128 / 4)
        *(float4*)&g_pool[idx * 4] = make_float4(0.f, 0.f, 0.f, 0.f);
}

__global__ void pool_kernel(const int* __restrict__ batch) {
    int idx = blockIdx.x * blockDim.x + threadIdx.x;
    int n = idx >> 5;
    if (n >= NN) return;
    int c4 = (idx & 31) << 2;
    float4 v = *(const float4*)&g_HS[(size_t)n * HSW + 384 + c4];
    float* p = g_pool + (size_t)batch[n] * 128 + c4;
    asm volatile("red.global.add.v4.f32 [%0], {%1,%2,%3,%4};"
                 :: "l"(p), "f"(v.x), "f"(v.y), "f"(v.z), "f"(v.w) : "memory");
}

__global__ void bcast_kernel(const int* __restrict__ batch) {
    int idx = blockIdx.x * blockDim.x + threadIdx.x;
    int n = idx >> 5;
    if (n >= NN) return;
    int c4 = (idx & 31) << 2;
    float4 v = *(const float4*)&g_pool[(size_t)batch[n] * 128 + c4];
    *(float4*)&g_HS[(size_t)n * HSW + 512 + c4] = v;
}

// ---------------------------------------------------------------------------
// Final: out[n] = sigmoid(Z1[n,:] . fW + fb)
// ---------------------------------------------------------------------------
__global__ void final_kernel(const float* __restrict__ Z,
                             const float* __restrict__ fW,
                             const float* __restrict__ fb,
                             float* __restrict__ out) {
    int idx = blockIdx.x * blockDim.x + threadIdx.x;
    int n = idx >> 5;
    if (n >= NN) return;
    int lane = idx & 31;
    float s = 0.f;
#pragma unroll
    for (int j = lane; j < CLSD; j += 32)
        s = fmaf(Z[(size_t)n * CLSD + j], fW[j], s);
#pragma unroll
    for (int o = 16; o; o >>= 1) s += __shfl_xor_sync(0xffffffffu, s, o);
    if (lane == 0) {
        float z = s + fb[0];
        out[n] = 1.f / (1.f + expf(-z));
    }
}

// ---------------------------------------------------------------------------
// Launch
// ---------------------------------------------------------------------------
extern "C" void kernel_launch(void* const* d_in, const int* in_sizes, int n_in,
                              void* d_out, int out_size) {
    const float* x    = (const float*)d_in[0];
    const int*   ei   = (const int*)d_in[1];
    const float* attr = (const float*)d_in[2];
    const int*   batch= (const int*)d_in[3];
    const float* c1W  = (const float*)d_in[4];
    const float* c1b  = (const float*)d_in[5];
    const float* c1g  = (const float*)d_in[6];
    const float* c1be = (const float*)d_in[7];
    const float* c1eW = (const float*)d_in[8];
    const float* c1eb = (const float*)d_in[9];
    const float* cW   = (const float*)d_in[10];
    const float* cb   = (const float*)d_in[11];
    const float* cg   = (const float*)d_in[12];
    const float* cbe  = (const float*)d_in[13];
    const float* ceW  = (const float*)d_in[14];
    const float* ceb  = (const float*)d_in[15];
    const float* k1W  = (const float*)d_in[16];
    const float* k1b  = (const float*)d_in[17];
    const float* kW   = (const float*)d_in[18];
    const float* kb   = (const float*)d_in[19];
    const float* fW   = (const float*)d_in[20];
    const float* fb   = (const float*)d_in[21];
    float* out = (float*)d_out;

    const int* srcp = ei;
    const int* dstp = ei + EE;

    const float bn_inv = (float)(1.0 / (double)((float)sqrt(1.0 + 1e-5)));

    float *agg, *h0, *HS, *z1, *z2;
    unsigned *Bh, *Bl;
    cudaGetSymbolAddress((void**)&agg, g_agg);
    cudaGetSymbolAddress((void**)&h0,  g_h0);
    cudaGetSymbolAddress((void**)&HS,  g_HS);
    cudaGetSymbolAddress((void**)&z1,  g_z1);
    cudaGetSymbolAddress((void**)&z2,  g_z2);
    cudaGetSymbolAddress((void**)&Bh,  g_Bh);
    cudaGetSymbolAddress((void**)&Bl,  g_Bl);

    // ---- CSR build + weight conversion (3 launches) ----
    wcvt_count_kernel<<<CNT_BLK + WCVT_BLK, 256>>>(dstp, c1W, cW, k1W, kW);
    csr_scan_kernel<<<1, 1024>>>();
    fill_permute_kernel<<<(EE * 4 + 255) / 256, 256>>>(srcp, dstp, attr);

    const int GATHER_BLOCKS = (NN * 32 + 127) / 128;

    // ---- conv1 (64 -> 128) ----
    {
        gather_kernel<64><<<GATHER_BLOCKS, 128>>>(x, INRR, c1eW, c1eb, agg);
        dim3 grid(1, (NN + 127) / 128);
        bf16_gemm<2><<<grid, 256>>>(agg, 64, Bh + WC1_OFF, Bl + WC1_OFF,
                                    c1b, c1g, c1be, h0, 128, NN, 64, 128, bn_inv);
    }

    // ---- conv loop (4 layers, 128 -> 128), outputs into HS cols i*128 ----
    for (int i = 0; i < 4; i++) {
        const float* inPtr = (i == 0) ? h0 : (HS + (size_t)(i - 1) * 128);
        int ldin = (i == 0) ? 128 : HSW;
        gather_kernel<128><<<GATHER_BLOCKS, 128>>>(inPtr, ldin,
                                                   ceW + (size_t)i * EDD * OUTD,
                                                   ceb + (size_t)i * OUTD, agg);
        dim3 grid(1, (NN + 127) / 128);
        bf16_gemm<2><<<grid, 256>>>(agg, 128,
                                    Bh + WCV_OFF + (size_t)i * 8192,
                                    Bl + WCV_OFF + (size_t)i * 8192,
                                    cb + (size_t)i * OUTD,
                                    cg + (size_t)i * OUTD,
                                    cbe + (size_t)i * OUTD,
                                    HS + (size_t)i * 128, HSW,
                                    NN, 128, 128, bn_inv);
    }

    // ---- global_add_pool + broadcast ----
    zero_pool_kernel<<<(NMOL * 128 / 4 + 255) / 256, 256>>>();
    pool_kernel<<<(NN * 32 + 255) / 256, 256>>>(batch);
    bcast_kernel<<<(NN * 32 + 255) / 256, 256>>>(batch);

    // ---- classifier ----
    {
        dim3 grid1(CLSD / 128, (NN + 127) / 128);
        bf16_gemm<0><<<grid1, 256>>>(HS, HSW, Bh + WK1_OFF, Bl + WK1_OFF,
                                     k1b, nullptr, nullptr,
                                     z1, CLSD, NN, HSW, CLSD, bn_inv);
        bf16_gemm<1><<<grid1, 256>>>(z1, CLSD, Bh + WK2_OFF, Bl + WK2_OFF,
                                     kb, nullptr, nullptr,
                                     z2, CLSD, NN, CLSD, CLSD, bn_inv);
        bf16_gemm<1><<<grid1, 256>>>(z2, CLSD, Bh + WK3_OFF, Bl + WK3_OFF,
                                     kb + CLSD, nullptr, nullptr,
                                     z1, CLSD, NN, CLSD, CLSD, bn_inv);
    }

    // ---- final dot + sigmoid ----
    final_kernel<<<(NN * 32 + 255) / 256, 256>>>(z1, fW, fb, out);
}